// round 10
// baseline (speedup 1.0000x reference)
#include <cuda_runtime.h>
#include <cuda_bf16.h>

// Single persistent kernel: stable 4-class counting sort + margin adjust +
// fused mean-NLL loss. Output: [data[N,4] | labels[N] | loss] float32.
//
// Warp-chunk design (1024 rows per warp-chunk):
//   Phase 1: per-chunk 4-bin histogram (int4 label reads).
//   Grid sync: last-arriving block scans chunk hists -> per-chunk offsets.
//   Phase 2: R3-style ballot-rank scatter (lowest-register hot loop measured),
//            labels re-read (L2-warm), analytic sorted-label fill, fused loss.
// __launch_bounds__(256, 8) caps regs at 32 -> full 2048 thr/SM residency,
// which is required for the spin sync (grid <= SMs * 8).

constexpr int TPB = 256;
constexpr int WPB = 8;
constexpr int CHUNK = 1024;            // rows per warp-chunk
constexpr int MAX_CHUNKS = 16384;

__device__ int4 g_chunkHist[MAX_CHUNKS];
__device__ int4 g_chunkOff[MAX_CHUNKS];
__device__ int4 g_classBase;
__device__ double g_loss;
__device__ unsigned g_histDone;
__device__ unsigned g_scatDone;
__device__ volatile unsigned g_flag;

static __device__ __forceinline__ int4 add4(int4 a, int4 b) {
    return make_int4(a.x + b.x, a.y + b.y, a.z + b.z, a.w + b.w);
}

__global__ void __launch_bounds__(TPB, 8)
fusedKernel(const float* __restrict__ data, const int* __restrict__ label,
            float* __restrict__ outData, float* __restrict__ outLabel,
            float* __restrict__ outLoss, int n, int numChunks) {
    __shared__ float warpLoss[WPB];
    __shared__ bool sScan;

    int tid = threadIdx.x;
    int w = tid >> 5;
    int lane = tid & 31;
    unsigned laneLT = (1u << lane) - 1u;
    int gw0 = blockIdx.x * WPB + w;
    int totalWarps = gridDim.x * WPB;
    int nv4 = n >> 2;

    // ---------------- Phase 1: per-chunk histograms -------------------------
    for (int ch = gw0; ch < numChunks; ch += totalWarps) {
        int base4 = ch * (CHUNK / 4);
        int c0 = 0, c1 = 0, c2 = 0, c3 = 0;
#pragma unroll
        for (int k = 0; k < CHUNK / 128; ++k) {        // 8 int4 loads per lane
            int vi = base4 + k * 32 + lane;
            if (vi < nv4) {
                int4 L = reinterpret_cast<const int4*>(label)[vi];
                c0 += (L.x == 0) + (L.y == 0) + (L.z == 0) + (L.w == 0);
                c1 += (L.x == 1) + (L.y == 1) + (L.z == 1) + (L.w == 1);
                c2 += (L.x == 2) + (L.y == 2) + (L.z == 2) + (L.w == 2);
                c3 += (L.x == 3) + (L.y == 3) + (L.z == 3) + (L.w == 3);
            }
        }
#pragma unroll
        for (int off = 16; off > 0; off >>= 1) {
            c0 += __shfl_down_sync(0xffffffffu, c0, off);
            c1 += __shfl_down_sync(0xffffffffu, c1, off);
            c2 += __shfl_down_sync(0xffffffffu, c2, off);
            c3 += __shfl_down_sync(0xffffffffu, c3, off);
        }
        if (lane == 0) g_chunkHist[ch] = make_int4(c0, c1, c2, c3);
    }

    // ---------------- Grid sync + scan by last-arriving block ---------------
    __threadfence();
    if (tid == 0) {
        unsigned t = atomicAdd(&g_histDone, 1u);
        sScan = (t == gridDim.x - 1);
        if (sScan) g_histDone = 0;                     // reset for graph replay
    }
    __syncthreads();

    if (sScan) {
        __shared__ int4 ss[TPB];
        int chunk = (numChunks + TPB - 1) / TPB;
        int start = tid * chunk;
        int end = min(start + chunk, numChunks);
        int4 s = make_int4(0, 0, 0, 0);
        for (int j = start; j < end; ++j) s = add4(s, g_chunkHist[j]);
        ss[tid] = s;
        __syncthreads();
        for (int off = 1; off < TPB; off <<= 1) {
            int4 v = ss[tid];
            if (tid >= off) v = add4(v, ss[tid - off]);
            __syncthreads();
            ss[tid] = v;
            __syncthreads();
        }
        int4 incl = ss[tid];
        int4 tot = ss[TPB - 1];
        int4 run;
        run.x = (incl.x - s.x);
        run.y = (incl.y - s.y) + tot.x;
        run.z = (incl.z - s.z) + tot.x + tot.y;
        run.w = (incl.w - s.w) + tot.x + tot.y + tot.z;
        for (int j = start; j < end; ++j) {
            int4 h = g_chunkHist[j];
            g_chunkOff[j] = run;
            run = add4(run, h);
        }
        if (tid == 0) {
            g_classBase = make_int4(0, tot.x, tot.x + tot.y,
                                    tot.x + tot.y + tot.z);
            g_loss = 0.0;
        }
        __syncthreads();
        __threadfence();
        if (tid == 0) g_flag = 1;                      // release
    } else {
        if (tid == 0) {
            while (g_flag == 0) __nanosleep(64);
        }
        __syncthreads();
        __threadfence();                               // acquire
    }

    // ---------------- Phase 2: ballot-rank scatter + labels + loss ----------
    int4 cb = g_classBase;
    float lsum = 0.0f;

    for (int ch = gw0; ch < numChunks; ch += totalWarps) {
        int4 wo = g_chunkOff[ch];
        int off0 = wo.x, off1 = wo.y, off2 = wo.z, off3 = wo.w;
        int rowBase = ch * CHUNK;

#pragma unroll 4
        for (int it = 0; it < CHUNK / 32; ++it) {      // 32 iterations
            int idx = rowBase + it * 32 + lane;
            bool valid = idx < n;
            int c = valid ? label[idx] : 4;            // L2-warm from phase 1

            unsigned m0 = __ballot_sync(0xffffffffu, c == 0);
            unsigned m1 = __ballot_sync(0xffffffffu, c == 1);
            unsigned m2 = __ballot_sync(0xffffffffu, c == 2);
            unsigned m3 = __ballot_sync(0xffffffffu, c == 3);

            if (valid) {
                unsigned myM = (c == 0) ? m0 : (c == 1) ? m1
                             : (c == 2) ? m2 : m3;
                int base = (c == 0) ? off0 : (c == 1) ? off1
                         : (c == 2) ? off2 : off3;
                int dest = base + __popc(myM & laneLT);

                float4 r = reinterpret_cast<const float4*>(data)[idx];
                float v = (c == 0) ? r.x : (c == 1) ? r.y
                        : (c == 2) ? r.z : r.w;
                float adj = (v > 0.0f) ? v * (1.0f / 4.00001f) - 0.5f
                                       : v * 4.00001f - 0.5f;
                if (c == 0) r.x = adj; else if (c == 1) r.y = adj;
                else if (c == 2) r.z = adj; else r.w = adj;

                // no max-subtraction: inputs ~N(0,1), |r|<6 -> no overflow
                float e = __expf(r.x) + __expf(r.y) +
                          __expf(r.z) + __expf(r.w);
                lsum += __logf(e) - adj;               // -log p[true]

                reinterpret_cast<float4*>(outData)[dest] = r;
            }
            off0 += __popc(m0); off1 += __popc(m1);
            off2 += __popc(m2); off3 += __popc(m3);
        }

        // analytic sorted-label fill for this chunk (streaming float4)
#pragma unroll
        for (int k = 0; k < CHUNK / 128; ++k) {        // 8 float4 per lane
            int p = rowBase + (k * 32 + lane) * 4;
            if (p < n) {
                float4 o;
                o.x = (float)((p     >= cb.y) + (p     >= cb.z) + (p     >= cb.w));
                o.y = (float)((p + 1 >= cb.y) + (p + 1 >= cb.z) + (p + 1 >= cb.w));
                o.z = (float)((p + 2 >= cb.y) + (p + 2 >= cb.z) + (p + 2 >= cb.w));
                o.w = (float)((p + 3 >= cb.y) + (p + 3 >= cb.z) + (p + 3 >= cb.w));
                reinterpret_cast<float4*>(outLabel)[p >> 2] = o;
            }
        }
    }

    // ---------------- loss reduce + final scalar ----------------------------
#pragma unroll
    for (int off = 16; off > 0; off >>= 1)
        lsum += __shfl_down_sync(0xffffffffu, lsum, off);
    if (lane == 0) warpLoss[w] = lsum;
    __syncthreads();
    if (tid == 0) {
        double sum = 0.0;
#pragma unroll
        for (int ww = 0; ww < WPB; ++ww) sum += (double)warpLoss[ww];
        atomicAdd(&g_loss, sum);
    }

    __threadfence();
    __shared__ bool isLast;
    if (tid == 0) {
        unsigned t = atomicAdd(&g_scatDone, 1u);
        isLast = (t == gridDim.x - 1);
    }
    __syncthreads();
    if (isLast && tid == 0) {
        g_scatDone = 0;
        g_flag = 0;                                    // reset for next replay
        double L = *((volatile double*)&g_loss);
        outLoss[0] = (float)(L / (double)n);
    }
}

extern "C" void kernel_launch(void* const* d_in, const int* in_sizes, int n_in,
                              void* d_out, int out_size) {
    const float* data = (const float*)d_in[0];
    const int* label = (const int*)d_in[1];
    float* out = (float*)d_out;
    int n = in_sizes[1];

    int sms = 148;
    cudaDeviceGetAttribute(&sms, cudaDevAttrMultiProcessorCount, 0);

    int numChunks = (n + CHUNK - 1) / CHUNK;
    int grid = (numChunks + WPB - 1) / WPB;
    int maxResident = sms * 8;                         // guaranteed by launch_bounds
    if (grid > maxResident) grid = maxResident;

    fusedKernel<<<grid, TPB>>>(data, label, out, out + (size_t)n * 4,
                               out + (size_t)n * 5, n, numChunks);
}

// round 11
// speedup vs baseline: 1.1221x; 1.1221x over previous
#include <cuda_runtime.h>
#include <cuda_bf16.h>

// Single persistent kernel: stable 4-class counting sort + margin adjust +
// fused mean-NLL loss. Output: [data[N,4] | labels[N] | loss] float32.
//
// Phase 1: read labels once (int4), cache packed 2-bit classes in smem,
//          per-tile + per-warp histograms.
// Grid sync: last-arriving block scans tile hists -> per-tile offsets.
// Phase 2: packed-count warp scan ranks 128 rows/warp (no ballots, no
//          loop-carried offsets); dests exchanged through smem so loads stay
//          lane-strided/coalesced; 2 rounds of MLP-2 per tile to keep regs
//          under the launch_bounds(256,7) cap; analytic label fill + loss.

constexpr int TPB = 256;
constexpr int WPB = 8;
constexpr int TILE = 1024;             // rows per tile
constexpr int T_PB_MAX = 12;
constexpr int MAX_TILES = 16384;
constexpr int RESIDENT_BPSM = 7;       // guaranteed by __launch_bounds__

__device__ int4 g_tileHist[MAX_TILES];
__device__ int4 g_tileOff[MAX_TILES];
__device__ int4 g_classBase;
__device__ double g_loss;
__device__ unsigned g_histDone;
__device__ unsigned g_scatDone;
__device__ volatile unsigned g_flag;

static __device__ __forceinline__ int4 add4(int4 a, int4 b) {
    return make_int4(a.x + b.x, a.y + b.y, a.z + b.z, a.w + b.w);
}

__global__ void __launch_bounds__(TPB, RESIDENT_BPSM)
fusedKernel(const float* __restrict__ data, const int* __restrict__ label,
            float* __restrict__ outData, float* __restrict__ outLabel,
            float* __restrict__ outLoss, int n, int numTiles) {
    __shared__ unsigned char sClass[T_PB_MAX][TILE / 4];  // 2 bits/row packed
    __shared__ int4 sWarpHist[T_PB_MAX][WPB];
    __shared__ int sDest[TILE];                           // (dest<<2)|class
    __shared__ float warpLoss[WPB];
    __shared__ bool sScan;

    int tid = threadIdx.x;
    int w = tid >> 5;
    int lane = tid & 31;

    int t0 = (int)(((long long)blockIdx.x * numTiles) / gridDim.x);
    int t1 = (int)(((long long)(blockIdx.x + 1) * numTiles) / gridDim.x);
    int nt = t1 - t0;
    int nv4 = n >> 2;

    // ---------------- Phase 1: labels -> smem classes + hists ---------------
    for (int s = 0; s < nt; ++s) {
        int tile = t0 + s;
        int vi = (tile * (TILE / 4)) + tid;          // rows 4vi..4vi+3
        int c0 = 0, c1 = 0, c2 = 0, c3 = 0;
        unsigned byte = 0;
        if (vi < nv4) {
            int4 L = reinterpret_cast<const int4*>(label)[vi];
            byte = (unsigned)(L.x | (L.y << 2) | (L.z << 4) | (L.w << 6));
            c0 = (L.x == 0) + (L.y == 0) + (L.z == 0) + (L.w == 0);
            c1 = (L.x == 1) + (L.y == 1) + (L.z == 1) + (L.w == 1);
            c2 = (L.x == 2) + (L.y == 2) + (L.z == 2) + (L.w == 2);
            c3 = (L.x == 3) + (L.y == 3) + (L.z == 3) + (L.w == 3);
        }
        sClass[s][tid] = (unsigned char)byte;
#pragma unroll
        for (int off = 16; off > 0; off >>= 1) {
            c0 += __shfl_down_sync(0xffffffffu, c0, off);
            c1 += __shfl_down_sync(0xffffffffu, c1, off);
            c2 += __shfl_down_sync(0xffffffffu, c2, off);
            c3 += __shfl_down_sync(0xffffffffu, c3, off);
        }
        if (lane == 0) sWarpHist[s][w] = make_int4(c0, c1, c2, c3);
    }
    __syncthreads();
    if (tid < nt) {
        int4 sum = make_int4(0, 0, 0, 0);
#pragma unroll
        for (int ww = 0; ww < WPB; ++ww) sum = add4(sum, sWarpHist[tid][ww]);
        g_tileHist[t0 + tid] = sum;
    }

    // ---------------- Grid sync + scan by last-arriving block ---------------
    __threadfence();
    if (tid == 0) {
        unsigned t = atomicAdd(&g_histDone, 1u);
        sScan = (t == gridDim.x - 1);
        if (sScan) g_histDone = 0;
    }
    __syncthreads();

    if (sScan) {
        __shared__ int4 ss[TPB];
        int chunk = (numTiles + TPB - 1) / TPB;
        int start = tid * chunk;
        int end = min(start + chunk, numTiles);
        int4 s = make_int4(0, 0, 0, 0);
        for (int j = start; j < end; ++j) s = add4(s, g_tileHist[j]);
        ss[tid] = s;
        __syncthreads();
        for (int off = 1; off < TPB; off <<= 1) {
            int4 v = ss[tid];
            if (tid >= off) v = add4(v, ss[tid - off]);
            __syncthreads();
            ss[tid] = v;
            __syncthreads();
        }
        int4 incl = ss[tid];
        int4 tot = ss[TPB - 1];
        int4 run;
        run.x = (incl.x - s.x);
        run.y = (incl.y - s.y) + tot.x;
        run.z = (incl.z - s.z) + tot.x + tot.y;
        run.w = (incl.w - s.w) + tot.x + tot.y + tot.z;
        for (int j = start; j < end; ++j) {
            int4 h = g_tileHist[j];
            g_tileOff[j] = run;
            run = add4(run, h);
        }
        if (tid == 0) {
            g_classBase = make_int4(0, tot.x, tot.x + tot.y,
                                    tot.x + tot.y + tot.z);
            g_loss = 0.0;
        }
        __syncthreads();
        __threadfence();
        if (tid == 0) g_flag = 1;
    } else {
        if (tid == 0) {
            while (g_flag == 0) __nanosleep(64);
        }
        __syncthreads();
        __threadfence();
    }

    // ---------------- Phase 2: rank via packed scan, coalesced scatter ------
    float lsum = 0.0f;

    for (int s = 0; s < nt; ++s) {
        int tile = t0 + s;

        // ---- rank this thread's 4 consecutive rows (rows 4*tid..4*tid+3) ---
        {
            int4 to = g_tileOff[tile];
            int base0 = to.x, base1 = to.y, base2 = to.z, base3 = to.w;
            for (int ww = 0; ww < w; ++ww) {
                int4 h = sWarpHist[s][ww];
                base0 += h.x; base1 += h.y; base2 += h.z; base3 += h.w;
            }
            unsigned byte = sClass[s][tid];
            int c0 = byte & 3, c1 = (byte >> 2) & 3;
            int c2 = (byte >> 4) & 3, c3 = (byte >> 6) & 3;
            unsigned cnt = (1u << (8 * c0)) + (1u << (8 * c1)) +
                           (1u << (8 * c2)) + (1u << (8 * c3));
            unsigned incl = cnt;
#pragma unroll
            for (int off = 1; off < 32; off <<= 1) {
                unsigned v = __shfl_up_sync(0xffffffffu, incl, off);
                if (lane >= off) incl += v;
            }
            unsigned excl = incl - cnt;
            base0 += excl & 0xff;
            base1 += (excl >> 8) & 0xff;
            base2 += (excl >> 16) & 0xff;
            base3 += (excl >> 24) & 0xff;

            int4 dpk;
            int* dv = &dpk.x;
#pragma unroll
            for (int k = 0; k < 4; ++k) {
                int c = (k == 0) ? c0 : (k == 1) ? c1 : (k == 2) ? c2 : c3;
                int dest;
                if (c == 0) dest = base0++;
                else if (c == 1) dest = base1++;
                else if (c == 2) dest = base2++;
                else dest = base3++;
                dv[k] = (dest << 2) | c;
            }
            reinterpret_cast<int4*>(sDest)[tid] = dpk;
        }
        __syncwarp();

        // ---- coalesced loads + process + scatter, 2 rounds of MLP-2 ---------
        {
            int rowT = w * 128 + lane;
            int idx0 = tile * TILE + rowT;
            const float4* dp = reinterpret_cast<const float4*>(data);

#pragma unroll
            for (int half = 0; half < 2; ++half) {
                int iA = idx0 + half * 64;
                int iB = iA + 32;
                float4 rA = make_float4(0.f, 0.f, 0.f, 0.f);
                float4 rB = rA;
                if (iA < n) rA = dp[iA];
                if (iB < n) rB = dp[iB];
                int dA = sDest[rowT + half * 64];
                int dB = sDest[rowT + half * 64 + 32];

#pragma unroll
                for (int k = 0; k < 2; ++k) {
                    int idx = (k == 0) ? iA : iB;
                    if (idx >= n) break;
                    float4 r = (k == 0) ? rA : rB;
                    int dpacked = (k == 0) ? dA : dB;
                    int c = dpacked & 3;
                    int dest = dpacked >> 2;

                    float v = (c == 0) ? r.x : (c == 1) ? r.y
                            : (c == 2) ? r.z : r.w;
                    float adj = (v > 0.0f) ? v * (1.0f / 4.00001f) - 0.5f
                                           : v * 4.00001f - 0.5f;
                    if (c == 0) r.x = adj; else if (c == 1) r.y = adj;
                    else if (c == 2) r.z = adj; else r.w = adj;

                    float mx = fmaxf(fmaxf(r.x, r.y), fmaxf(r.z, r.w));
                    float lse = mx + __logf(__expf(r.x - mx) + __expf(r.y - mx) +
                                            __expf(r.z - mx) + __expf(r.w - mx));
                    lsum += lse - adj;

                    reinterpret_cast<float4*>(outData)[dest] = r;
                }
            }
        }

        // ---- analytic sorted-label fill (streaming float4) ------------------
        {
            int4 cb = g_classBase;
            int p = tile * TILE + tid * 4;
            if (p < n) {
                float4 o;
                o.x = (float)((p     >= cb.y) + (p     >= cb.z) + (p     >= cb.w));
                o.y = (float)((p + 1 >= cb.y) + (p + 1 >= cb.z) + (p + 1 >= cb.w));
                o.z = (float)((p + 2 >= cb.y) + (p + 2 >= cb.z) + (p + 2 >= cb.w));
                o.w = (float)((p + 3 >= cb.y) + (p + 3 >= cb.z) + (p + 3 >= cb.w));
                reinterpret_cast<float4*>(outLabel)[p >> 2] = o;
            }
        }
        __syncwarp();   // protect sDest reuse next tile (warp-private region)
    }

    // ---------------- loss reduce + final scalar ----------------------------
#pragma unroll
    for (int off = 16; off > 0; off >>= 1)
        lsum += __shfl_down_sync(0xffffffffu, lsum, off);
    if (lane == 0) warpLoss[w] = lsum;
    __syncthreads();
    if (tid == 0) {
        double sum = 0.0;
#pragma unroll
        for (int ww = 0; ww < WPB; ++ww) sum += (double)warpLoss[ww];
        atomicAdd(&g_loss, sum);
    }

    __threadfence();
    __shared__ bool isLast;
    if (tid == 0) {
        unsigned t = atomicAdd(&g_scatDone, 1u);
        isLast = (t == gridDim.x - 1);
    }
    __syncthreads();
    if (isLast && tid == 0) {
        g_scatDone = 0;
        g_flag = 0;
        double L = *((volatile double*)&g_loss);
        outLoss[0] = (float)(L / (double)n);
    }
}

extern "C" void kernel_launch(void* const* d_in, const int* in_sizes, int n_in,
                              void* d_out, int out_size) {
    const float* data = (const float*)d_in[0];
    const int* label = (const int*)d_in[1];
    float* out = (float*)d_out;
    int n = in_sizes[1];

    int sms = 148;
    cudaDeviceGetAttribute(&sms, cudaDevAttrMultiProcessorCount, 0);

    int numTiles = (n + TILE - 1) / TILE;
    int grid = sms * RESIDENT_BPSM;          // co-resident by launch_bounds
    if (grid > numTiles) grid = numTiles;
    int minGrid = (numTiles + T_PB_MAX - 1) / T_PB_MAX;
    if (grid < minGrid) grid = minGrid;

    fusedKernel<<<grid, TPB>>>(data, label, out, out + (size_t)n * 4,
                               out + (size_t)n * 5, n, numTiles);
}